// round 8
// baseline (speedup 1.0000x reference)
#include <cuda_runtime.h>
#include <cstdint>

// scGNN: 2-layer GCN on GB300.
//   out = A·relu(A·(x@W1) + b1) @ W2 + b2, A = sym-norm adjacency w/ self-loops.
// Layer-2 aggregation is commuted past W2 so both scatters are 32-wide.
// Scatter: 1 thread/edge, one packed 16B edge record {s*32, d*32, norm},
// 8 contiguous gather LDG.128 + 8 RED.128 (v4 fire-and-forget atomics).

#define NN   100000
#define EE   1200000
#define FIN  64
#define FMID 32

static __device__ int   g_is64;
static __device__ __align__(16) float g_deg [NN];         // raw degree (incl self)
static __device__ __align__(16) int4  g_edge[EE];         // {s*32, d*32, norm, 0}
static __device__ __align__(16) float g_h1[NN * FMID];    // x @ W1
static __device__ __align__(16) float g_a1[NN * FMID];    // layer-1 aggregate
static __device__ __align__(16) float g_r [NN * FMID];    // relu(a1+b1)
static __device__ __align__(16) float g_a2[NN * FMID];    // layer-2 aggregate

// ---------------------------------------------------------------------------
__device__ __forceinline__ void red_add_v4(float* addr, float a, float b,
                                           float c, float d) {
    asm volatile("red.global.add.v4.f32 [%0], {%1, %2, %3, %4};"
                 :: "l"(addr), "f"(a), "f"(b), "f"(c), "f"(d)
                 : "memory");
}

__device__ __forceinline__ int get_idx(const void* ei, int pos) {
    int v = g_is64 ? (int)((const long long*)ei)[pos]
                   : ((const int*)ei)[pos];
    return min(max(v, 0), NN - 1);
}

// ---------------------------------------------------------------------------
// deg := 1 (self-loop) ; block 0 also detects edge-index dtype.
__global__ void k_init(const int* __restrict__ ei, int n) {
    int i = blockIdx.x * blockDim.x + threadIdx.x;
    if (i < n) g_deg[i] = 1.0f;
    if (blockIdx.x == 0) {
        __shared__ int nz;
        if (threadIdx.x == 0) nz = 0;
        __syncthreads();
        for (int k = threadIdx.x; k < 2048; k += blockDim.x)
            if (ei[2 * k + 1] != 0) nz = 1;
        __syncthreads();
        if (threadIdx.x == 0) g_is64 = (nz == 0) ? 1 : 0;
    }
}

// In-degree histogram.
__global__ void k_deg_count(const void* __restrict__ ei, int E) {
    int e = blockIdx.x * blockDim.x + threadIdx.x;
    if (e < E) atomicAdd(&g_deg[get_idx(ei, E + e)], 1.0f);
}

// Packed edge records: norm = rsqrt(deg_s * deg_d) == dinv_s * dinv_d.
__global__ void k_edge_fin(const void* __restrict__ ei, int E) {
    int e = blockIdx.x * blockDim.x + threadIdx.x;
    if (e >= E) return;
    int s = get_idx(ei, e);
    int d = get_idx(ei, E + e);
    float nm = rsqrtf(g_deg[s] * g_deg[d]);
    g_edge[e] = make_int4(s * FMID, d * FMID, __float_as_int(nm), 0);
}

// ---------------------------------------------------------------------------
// GEMM1 (+ fused a1 self-loop init): h1 = x@W1 ; a1 = h1 / deg.
__global__ void k_gemm1(const float* __restrict__ x,
                        const float* __restrict__ W1, int n) {
    __shared__ float sW[FIN * FMID];  // 8 KB
    for (int i = threadIdx.x; i < FIN * FMID; i += blockDim.x)
        sW[i] = W1[i];
    __syncthreads();

    int warp = threadIdx.x >> 5;
    int lane = threadIdx.x & 31;
    int row  = blockIdx.x * 8 + warp;
    if (row >= n) return;

    float xa = x[row * FIN + lane];
    float xb = x[row * FIN + 32 + lane];
    float acc = 0.0f;
#pragma unroll
    for (int k = 0; k < 32; k++)
        acc += __shfl_sync(0xffffffffu, xa, k) * sW[k * FMID + lane];
#pragma unroll
    for (int k = 0; k < 32; k++)
        acc += __shfl_sync(0xffffffffu, xb, k) * sW[(k + 32) * FMID + lane];

    float w = 1.0f / g_deg[row];     // dinv^2
    g_h1[row * FMID + lane] = acc;
    g_a1[row * FMID + lane] = w * acc;
}

// 32-wide edge scatter, 1 thread/edge. which=0: h1->a1, which=1: r->a2.
// All 8 gathers batched first (MLP=8, one 128B row), then 8 v4 REDs.
__global__ void __launch_bounds__(256) k_scatter32(int which, int E) {
    int e = blockIdx.x * blockDim.x + threadIdx.x;
    if (e >= E) return;
    const float* __restrict__ src = which ? g_r  : g_h1;
    float*       __restrict__ dst = which ? g_a2 : g_a1;

    int4  rec = g_edge[e];
    float nm  = __int_as_float(rec.z);
    const float4* sp = reinterpret_cast<const float4*>(&src[rec.x]);

    float4 v[8];
#pragma unroll
    for (int j = 0; j < 8; j++) v[j] = sp[j];

    float* o = &dst[rec.y];
#pragma unroll
    for (int j = 0; j < 8; j++)
        red_add_v4(o + 4 * j, v[j].x * nm, v[j].y * nm, v[j].z * nm, v[j].w * nm);
}

// r := relu(a1 + b1) ; a2 := r / deg (self-loop init). float4-vectorized.
__global__ void k_relu(const float* __restrict__ b1, int n) {
    int idx = blockIdx.x * blockDim.x + threadIdx.x;   // n*8 float4 slots
    if (idx >= n * (FMID / 4)) return;
    int i = idx >> 3;
    int c = (idx & 7) * 4;
    float w = 1.0f / g_deg[i];
    float4 a  = reinterpret_cast<const float4*>(g_a1)[idx];
    float4 bb = *reinterpret_cast<const float4*>(&b1[c]);
    float4 r;
    r.x = fmaxf(a.x + bb.x, 0.0f);
    r.y = fmaxf(a.y + bb.y, 0.0f);
    r.z = fmaxf(a.z + bb.z, 0.0f);
    r.w = fmaxf(a.w + bb.w, 0.0f);
    reinterpret_cast<float4*>(g_r)[idx] = r;
    reinterpret_cast<float4*>(g_a2)[idx] =
        make_float4(w * r.x, w * r.y, w * r.z, w * r.w);
}

// GEMM2: out = a2 @ W2 + b2.  One warp per row; lane owns cols {lane, lane+32}.
__global__ void k_gemm2(const float* __restrict__ W2,
                        const float* __restrict__ b2,
                        float* __restrict__ out, int n) {
    __shared__ float sW[FMID * FIN];  // 8 KB
    for (int i = threadIdx.x; i < FMID * FIN; i += blockDim.x)
        sW[i] = W2[i];
    __syncthreads();

    int warp = threadIdx.x >> 5;
    int lane = threadIdx.x & 31;
    int row  = blockIdx.x * 8 + warp;
    if (row >= n) return;

    float a = g_a2[row * FMID + lane];
    float acc0 = 0.0f, acc1 = 0.0f;
#pragma unroll
    for (int k = 0; k < 32; k++) {
        float ak = __shfl_sync(0xffffffffu, a, k);
        acc0 += ak * sW[k * FIN + lane];
        acc1 += ak * sW[k * FIN + 32 + lane];
    }
    out[row * FIN + lane]      = acc0 + b2[lane];
    out[row * FIN + 32 + lane] = acc1 + b2[32 + lane];
}

// ---------------------------------------------------------------------------
extern "C" void kernel_launch(void* const* d_in, const int* in_sizes, int n_in,
                              void* d_out, int out_size) {
    const float* x  = (const float*)d_in[0];
    const void*  ei = d_in[1];                 // edge_index [2,E], int32
    const float* W1 = (const float*)d_in[2];
    const float* b1 = (const float*)d_in[3];
    const float* W2 = (const float*)d_in[4];
    const float* b2 = (const float*)d_in[5];
    float*       out = (float*)d_out;

    const int N = in_sizes[0] / FIN;   // 100000
    const int E = in_sizes[1] / 2;     // 1200000

    const int T = 256;
    k_init     <<<(N + T - 1) / T, T>>>((const int*)ei, N);
    k_deg_count<<<(E + T - 1) / T, T>>>(ei, E);
    k_edge_fin <<<(E + T - 1) / T, T>>>(ei, E);

    k_gemm1    <<<(N + 7) / 8, T>>>(x, W1, N);
    k_scatter32<<<(E + T - 1) / T, T>>>(0, E);

    k_relu     <<<(N * (FMID / 4) + T - 1) / T, T>>>(b1, N);
    k_scatter32<<<(E + T - 1) / T, T>>>(1, E);

    k_gemm2    <<<(N + 7) / 8, T>>>(W2, b2, out, N);
}

// round 9
// speedup vs baseline: 1.4587x; 1.4587x over previous
#include <cuda_runtime.h>
#include <cstdint>

// scGNN: 2-layer GCN on GB300.
//   out = A·relu(A·(x@W1) + b1) @ W2 + b2, A = sym-norm adjacency w/ self-loops.
// Layer-2 aggregation commuted past W2 -> both scatters 32-wide.
// Scatters: 4 threads/edge (lane-contiguous 16B chunks of one 128B row ->
// ~1 wavefront/instr), packed 16B edge record {s*32, d*32, norm}.
// GEMMs: register-tiled (4x8 acc per lane), ~6 LDS + 64 FFMA per node.

#define NN   100000
#define EE   1200000
#define FIN  64
#define FMID 32

static __device__ int   g_is64;
static __device__ __align__(16) float g_deg [NN];         // raw degree (incl self)
static __device__ __align__(16) int4  g_edge[EE];         // {s*32, d*32, norm, 0}
static __device__ __align__(16) float g_h1[NN * FMID];    // x @ W1
static __device__ __align__(16) float g_a1[NN * FMID];    // layer-1 aggregate
static __device__ __align__(16) float g_r [NN * FMID];    // relu(a1+b1)
static __device__ __align__(16) float g_a2[NN * FMID];    // layer-2 aggregate

// ---------------------------------------------------------------------------
__device__ __forceinline__ void red_add_v4(float* addr, float a, float b,
                                           float c, float d) {
    asm volatile("red.global.add.v4.f32 [%0], {%1, %2, %3, %4};"
                 :: "l"(addr), "f"(a), "f"(b), "f"(c), "f"(d)
                 : "memory");
}

__device__ __forceinline__ int get_idx(const void* ei, int pos) {
    int v = g_is64 ? (int)((const long long*)ei)[pos]
                   : ((const int*)ei)[pos];
    return min(max(v, 0), NN - 1);
}

// ---------------------------------------------------------------------------
// deg := 1 (self-loop) ; block 0 also detects edge-index dtype.
__global__ void k_init(const int* __restrict__ ei, int n) {
    int i = blockIdx.x * blockDim.x + threadIdx.x;
    if (i < n) g_deg[i] = 1.0f;
    if (blockIdx.x == 0) {
        __shared__ int nz;
        if (threadIdx.x == 0) nz = 0;
        __syncthreads();
        for (int k = threadIdx.x; k < 2048; k += blockDim.x)
            if (ei[2 * k + 1] != 0) nz = 1;
        __syncthreads();
        if (threadIdx.x == 0) g_is64 = (nz == 0) ? 1 : 0;
    }
}

__global__ void k_deg_count(const void* __restrict__ ei, int E) {
    int e = blockIdx.x * blockDim.x + threadIdx.x;
    if (e < E) atomicAdd(&g_deg[get_idx(ei, E + e)], 1.0f);
}

// Packed edge records: norm = rsqrt(deg_s * deg_d) == dinv_s * dinv_d.
__global__ void k_edge_fin(const void* __restrict__ ei, int E) {
    int e = blockIdx.x * blockDim.x + threadIdx.x;
    if (e >= E) return;
    int s = get_idx(ei, e);
    int d = get_idx(ei, E + e);
    float nm = rsqrtf(g_deg[s] * g_deg[d]);
    g_edge[e] = make_int4(s * FMID, d * FMID, __float_as_int(nm), 0);
}

// ---------------------------------------------------------------------------
// GEMM1 (register-tiled): h1 = x@W1 ; a1 = h1/deg. Block=128 thr, 128 nodes.
// Warp tile 32 nodes x 32 cols; lane tile 4 nodes x 8 cols.
__global__ void __launch_bounds__(128) k_gemm1(const float* __restrict__ x,
                                               const float* __restrict__ W1,
                                               int n) {
    __shared__ float xs[64 * 132];   // x transposed [k][node], pad 4 (33 KB)
    __shared__ float ws[64 * 32];    // W1 [k][col] (8 KB)
    int tid  = threadIdx.x;
    int base = blockIdx.x * 128;

    for (int i = tid; i < 64 * 32; i += 128) ws[i] = W1[i];
    for (int i = tid; i < 128 * 64; i += 128) {
        int node = i >> 6, k = i & 63;
        xs[k * 132 + node] =
            (base + node < n) ? x[(base + node) * FIN + k] : 0.0f;
    }
    __syncthreads();

    int warp = tid >> 5, lane = tid & 31;
    int n0 = warp * 32 + (lane >> 2) * 4;   // node offset in block tile
    int c0 = (lane & 3) * 8;                // col offset

    float acc[4][8];
#pragma unroll
    for (int i = 0; i < 4; i++)
#pragma unroll
        for (int j = 0; j < 8; j++) acc[i][j] = 0.0f;

#pragma unroll 4
    for (int k = 0; k < 64; k++) {
        float4 xv = *reinterpret_cast<const float4*>(&xs[k * 132 + n0]);
        float4 wa = *reinterpret_cast<const float4*>(&ws[k * 32 + c0]);
        float4 wb = *reinterpret_cast<const float4*>(&ws[k * 32 + c0 + 4]);
        float xr[4] = {xv.x, xv.y, xv.z, xv.w};
        float wr[8] = {wa.x, wa.y, wa.z, wa.w, wb.x, wb.y, wb.z, wb.w};
#pragma unroll
        for (int i = 0; i < 4; i++)
#pragma unroll
            for (int j = 0; j < 8; j++) acc[i][j] += xr[i] * wr[j];
    }

#pragma unroll
    for (int i = 0; i < 4; i++) {
        int node = base + n0 + i;
        if (node >= n) break;
        float w = 1.0f / g_deg[node];
        float4 h0 = make_float4(acc[i][0], acc[i][1], acc[i][2], acc[i][3]);
        float4 h1 = make_float4(acc[i][4], acc[i][5], acc[i][6], acc[i][7]);
        *reinterpret_cast<float4*>(&g_h1[node * FMID + c0])     = h0;
        *reinterpret_cast<float4*>(&g_h1[node * FMID + c0 + 4]) = h1;
        *reinterpret_cast<float4*>(&g_a1[node * FMID + c0]) =
            make_float4(w * h0.x, w * h0.y, w * h0.z, w * h0.w);
        *reinterpret_cast<float4*>(&g_a1[node * FMID + c0 + 4]) =
            make_float4(w * h1.x, w * h1.y, w * h1.z, w * h1.w);
    }
}

// 32-wide edge scatter, 4 threads/edge (R7 shape + packed record).
// which=0: h1->a1, which=1: r->a2.
__global__ void __launch_bounds__(256) k_scatter32(int which, int E) {
    int t = blockIdx.x * blockDim.x + threadIdx.x;
    if (t >= E * 4) return;
    const float* __restrict__ src = which ? g_r  : g_h1;
    float*       __restrict__ dst = which ? g_a2 : g_a1;
    int e = t >> 2;
    int q = (t & 3) * 8;
    int4  rec = g_edge[e];
    float nm  = __int_as_float(rec.z);
    const float4* sp = reinterpret_cast<const float4*>(&src[rec.x + q]);
    float4 v0 = sp[0];
    float4 v1 = sp[1];
    float* o = &dst[rec.y + q];
    red_add_v4(o,     v0.x * nm, v0.y * nm, v0.z * nm, v0.w * nm);
    red_add_v4(o + 4, v1.x * nm, v1.y * nm, v1.z * nm, v1.w * nm);
}

// r := relu(a1 + b1) ; a2 := r/deg (self-loop init). float4-vectorized.
__global__ void k_relu(const float* __restrict__ b1, int n) {
    int idx = blockIdx.x * blockDim.x + threadIdx.x;   // n*8 float4 slots
    if (idx >= n * (FMID / 4)) return;
    int i = idx >> 3;
    int c = (idx & 7) * 4;
    float w = 1.0f / g_deg[i];
    float4 a  = reinterpret_cast<const float4*>(g_a1)[idx];
    float4 bb = *reinterpret_cast<const float4*>(&b1[c]);
    float4 r;
    r.x = fmaxf(a.x + bb.x, 0.0f);
    r.y = fmaxf(a.y + bb.y, 0.0f);
    r.z = fmaxf(a.z + bb.z, 0.0f);
    r.w = fmaxf(a.w + bb.w, 0.0f);
    reinterpret_cast<float4*>(g_r)[idx] = r;
    reinterpret_cast<float4*>(g_a2)[idx] =
        make_float4(w * r.x, w * r.y, w * r.z, w * r.w);
}

// GEMM2 (register-tiled): out = a2@W2 + b2. Block=128 thr, 64 nodes.
// Warp tile 16 nodes x 64 cols; lane tile 4 nodes x 8 cols.
__global__ void __launch_bounds__(128) k_gemm2(const float* __restrict__ W2,
                                               const float* __restrict__ b2,
                                               float* __restrict__ out, int n) {
    __shared__ float as_[32 * 68];   // a2 transposed [k][node], pad 4 (8.7 KB)
    __shared__ float ws[32 * 64];    // W2 [k][col] (8 KB)
    int tid  = threadIdx.x;
    int base = blockIdx.x * 64;

    for (int i = tid; i < 32 * 64; i += 128) ws[i] = W2[i];
    for (int i = tid; i < 64 * 32; i += 128) {
        int node = i >> 5, k = i & 31;
        as_[k * 68 + node] =
            (base + node < n) ? g_a2[(base + node) * FMID + k] : 0.0f;
    }
    __syncthreads();

    int warp = tid >> 5, lane = tid & 31;
    int n0 = warp * 16 + (lane >> 3) * 4;   // node offset in block tile
    int c0 = (lane & 7) * 8;                // col offset

    float acc[4][8];
#pragma unroll
    for (int i = 0; i < 4; i++)
#pragma unroll
        for (int j = 0; j < 8; j++) acc[i][j] = 0.0f;

#pragma unroll 4
    for (int k = 0; k < 32; k++) {
        float4 xv = *reinterpret_cast<const float4*>(&as_[k * 68 + n0]);
        float4 wa = *reinterpret_cast<const float4*>(&ws[k * 64 + c0]);
        float4 wb = *reinterpret_cast<const float4*>(&ws[k * 64 + c0 + 4]);
        float xr[4] = {xv.x, xv.y, xv.z, xv.w};
        float wr[8] = {wa.x, wa.y, wa.z, wa.w, wb.x, wb.y, wb.z, wb.w};
#pragma unroll
        for (int i = 0; i < 4; i++)
#pragma unroll
            for (int j = 0; j < 8; j++) acc[i][j] += xr[i] * wr[j];
    }

    float4 ba = *reinterpret_cast<const float4*>(&b2[c0]);
    float4 bbv = *reinterpret_cast<const float4*>(&b2[c0 + 4]);
#pragma unroll
    for (int i = 0; i < 4; i++) {
        int node = base + n0 + i;
        if (node >= n) break;
        *reinterpret_cast<float4*>(&out[node * FIN + c0]) =
            make_float4(acc[i][0] + ba.x, acc[i][1] + ba.y,
                        acc[i][2] + ba.z, acc[i][3] + ba.w);
        *reinterpret_cast<float4*>(&out[node * FIN + c0 + 4]) =
            make_float4(acc[i][4] + bbv.x, acc[i][5] + bbv.y,
                        acc[i][6] + bbv.z, acc[i][7] + bbv.w);
    }
}

// ---------------------------------------------------------------------------
extern "C" void kernel_launch(void* const* d_in, const int* in_sizes, int n_in,
                              void* d_out, int out_size) {
    const float* x  = (const float*)d_in[0];
    const void*  ei = d_in[1];                 // edge_index [2,E], int32
    const float* W1 = (const float*)d_in[2];
    const float* b1 = (const float*)d_in[3];
    const float* W2 = (const float*)d_in[4];
    const float* b2 = (const float*)d_in[5];
    float*       out = (float*)d_out;

    const int N = in_sizes[0] / FIN;   // 100000
    const int E = in_sizes[1] / 2;     // 1200000

    const int T = 256;
    k_init     <<<(N + T - 1) / T, T>>>((const int*)ei, N);
    k_deg_count<<<(E + T - 1) / T, T>>>(ei, E);
    k_edge_fin <<<(E + T - 1) / T, T>>>(ei, E);

    k_gemm1    <<<(N + 127) / 128, 128>>>(x, W1, N);
    k_scatter32<<<(E * 4 + T - 1) / T, T>>>(0, E);

    k_relu     <<<(N * (FMID / 4) + T - 1) / T, T>>>(b1, N);
    k_scatter32<<<(E * 4 + T - 1) / T, T>>>(1, E);

    k_gemm2    <<<(N + 63) / 64, 128>>>(W2, b2, out, N);
}

// round 10
// speedup vs baseline: 1.6913x; 1.1594x over previous
#include <cuda_runtime.h>
#include <cstdint>

// scGNN: 2-layer GCN on GB300.
//   out = A·relu(A·(x@W1) + b1) @ W2 + b2, A = sym-norm adjacency w/ self-loops.
// Layer-2 aggregation commuted past W2 -> both scatters 32-wide.
// Scatters: 8 threads/edge -> each edge's 128B row covered by ONE gather
// LDG.128 wavefront + ONE RED.128 wavefront (minimum possible).
// GEMMs: register-tiled outer product; gemm1 at 256 thr/block for occupancy.

#define NN   100000
#define EE   1200000
#define FIN  64
#define FMID 32

static __device__ int   g_is64;
static __device__ __align__(16) float g_deg [NN];         // raw degree (incl self)
static __device__ __align__(16) int4  g_edge[EE];         // {s*32, d*32, norm, 0}
static __device__ __align__(16) float g_h1[NN * FMID];    // x @ W1
static __device__ __align__(16) float g_a1[NN * FMID];    // layer-1 aggregate
static __device__ __align__(16) float g_r [NN * FMID];    // relu(a1+b1)
static __device__ __align__(16) float g_a2[NN * FMID];    // layer-2 aggregate

// ---------------------------------------------------------------------------
__device__ __forceinline__ void red_add_v4(float* addr, float a, float b,
                                           float c, float d) {
    asm volatile("red.global.add.v4.f32 [%0], {%1, %2, %3, %4};"
                 :: "l"(addr), "f"(a), "f"(b), "f"(c), "f"(d)
                 : "memory");
}

__device__ __forceinline__ int get_idx(const void* ei, int pos) {
    int v = g_is64 ? (int)((const long long*)ei)[pos]
                   : ((const int*)ei)[pos];
    return min(max(v, 0), NN - 1);
}

// ---------------------------------------------------------------------------
// deg := 1 (self-loop) ; block 0 also detects edge-index dtype.
__global__ void k_init(const int* __restrict__ ei, int n) {
    int i = blockIdx.x * blockDim.x + threadIdx.x;
    if (i < n) g_deg[i] = 1.0f;
    if (blockIdx.x == 0) {
        __shared__ int nz;
        if (threadIdx.x == 0) nz = 0;
        __syncthreads();
        for (int k = threadIdx.x; k < 2048; k += blockDim.x)
            if (ei[2 * k + 1] != 0) nz = 1;
        __syncthreads();
        if (threadIdx.x == 0) g_is64 = (nz == 0) ? 1 : 0;
    }
}

__global__ void k_deg_count(const void* __restrict__ ei, int E) {
    int e = blockIdx.x * blockDim.x + threadIdx.x;
    if (e < E) atomicAdd(&g_deg[get_idx(ei, E + e)], 1.0f);
}

// Packed edge records: norm = rsqrt(deg_s * deg_d) == dinv_s * dinv_d.
__global__ void k_edge_fin(const void* __restrict__ ei, int E) {
    int e = blockIdx.x * blockDim.x + threadIdx.x;
    if (e >= E) return;
    int s = get_idx(ei, e);
    int d = get_idx(ei, E + e);
    float nm = rsqrtf(g_deg[s] * g_deg[d]);
    g_edge[e] = make_int4(s * FMID, d * FMID, __float_as_int(nm), 0);
}

// ---------------------------------------------------------------------------
// GEMM1 (register-tiled): h1 = x@W1 ; a1 = h1/deg.
// Block = 256 thr, 128 nodes. Warp: 16 nodes x 32 cols; lane: 2 nodes x 8 cols.
__global__ void __launch_bounds__(256) k_gemm1(const float* __restrict__ x,
                                               const float* __restrict__ W1,
                                               int n) {
    __shared__ float xs[64 * 132];   // x transposed [k][node], pad 4 (33 KB)
    __shared__ float ws[64 * 32];    // W1 [k][col] (8 KB)
    int tid  = threadIdx.x;
    int base = blockIdx.x * 128;

    for (int i = tid; i < 64 * 32; i += 256) ws[i] = W1[i];
    for (int i = tid; i < 128 * 64; i += 256) {
        int node = i >> 6, k = i & 63;
        xs[k * 132 + node] =
            (base + node < n) ? x[(base + node) * FIN + k] : 0.0f;
    }
    __syncthreads();

    int warp = tid >> 5, lane = tid & 31;
    int n0 = warp * 16 + (lane >> 2) * 2;   // node offset in block tile
    int c0 = (lane & 3) * 8;                // col offset

    float acc[2][8];
#pragma unroll
    for (int i = 0; i < 2; i++)
#pragma unroll
        for (int j = 0; j < 8; j++) acc[i][j] = 0.0f;

#pragma unroll 8
    for (int k = 0; k < 64; k++) {
        float2 xv = *reinterpret_cast<const float2*>(&xs[k * 132 + n0]);
        float4 wa = *reinterpret_cast<const float4*>(&ws[k * 32 + c0]);
        float4 wb = *reinterpret_cast<const float4*>(&ws[k * 32 + c0 + 4]);
        float xr[2] = {xv.x, xv.y};
        float wr[8] = {wa.x, wa.y, wa.z, wa.w, wb.x, wb.y, wb.z, wb.w};
#pragma unroll
        for (int i = 0; i < 2; i++)
#pragma unroll
            for (int j = 0; j < 8; j++) acc[i][j] += xr[i] * wr[j];
    }

#pragma unroll
    for (int i = 0; i < 2; i++) {
        int node = base + n0 + i;
        if (node >= n) break;
        float w = 1.0f / g_deg[node];
        float4 h0 = make_float4(acc[i][0], acc[i][1], acc[i][2], acc[i][3]);
        float4 h1 = make_float4(acc[i][4], acc[i][5], acc[i][6], acc[i][7]);
        *reinterpret_cast<float4*>(&g_h1[node * FMID + c0])     = h0;
        *reinterpret_cast<float4*>(&g_h1[node * FMID + c0 + 4]) = h1;
        *reinterpret_cast<float4*>(&g_a1[node * FMID + c0]) =
            make_float4(w * h0.x, w * h0.y, w * h0.z, w * h0.w);
        *reinterpret_cast<float4*>(&g_a1[node * FMID + c0 + 4]) =
            make_float4(w * h1.x, w * h1.y, w * h1.z, w * h1.w);
    }
}

// 32-wide edge scatter, 8 threads/edge: one LDG.128 + one RED.128 each.
// which=0: h1->a1, which=1: r->a2.
__global__ void __launch_bounds__(256) k_scatter32(int which, int E) {
    int t = blockIdx.x * blockDim.x + threadIdx.x;
    if (t >= E * 8) return;
    const float* __restrict__ src = which ? g_r  : g_h1;
    float*       __restrict__ dst = which ? g_a2 : g_a1;
    int e = t >> 3;
    int q = (t & 7) * 4;
    int4  rec = g_edge[e];      // 8 lanes same address -> broadcast
    float nm  = __int_as_float(rec.z);
    float4 v = *reinterpret_cast<const float4*>(&src[rec.x + q]);
    red_add_v4(&dst[rec.y + q], v.x * nm, v.y * nm, v.z * nm, v.w * nm);
}

// r := relu(a1 + b1) ; a2 := r/deg (self-loop init). float4-vectorized.
__global__ void k_relu(const float* __restrict__ b1, int n) {
    int idx = blockIdx.x * blockDim.x + threadIdx.x;   // n*8 float4 slots
    if (idx >= n * (FMID / 4)) return;
    int i = idx >> 3;
    int c = (idx & 7) * 4;
    float w = 1.0f / g_deg[i];
    float4 a  = reinterpret_cast<const float4*>(g_a1)[idx];
    float4 bb = *reinterpret_cast<const float4*>(&b1[c]);
    float4 r;
    r.x = fmaxf(a.x + bb.x, 0.0f);
    r.y = fmaxf(a.y + bb.y, 0.0f);
    r.z = fmaxf(a.z + bb.z, 0.0f);
    r.w = fmaxf(a.w + bb.w, 0.0f);
    reinterpret_cast<float4*>(g_r)[idx] = r;
    reinterpret_cast<float4*>(g_a2)[idx] =
        make_float4(w * r.x, w * r.y, w * r.z, w * r.w);
}

// GEMM2 (register-tiled): out = a2@W2 + b2. Block=128 thr, 64 nodes.
// Warp tile 16 nodes x 64 cols; lane tile 4 nodes x 8 cols.
__global__ void __launch_bounds__(128) k_gemm2(const float* __restrict__ W2,
                                               const float* __restrict__ b2,
                                               float* __restrict__ out, int n) {
    __shared__ float as_[32 * 68];   // a2 transposed [k][node], pad 4 (8.7 KB)
    __shared__ float ws[32 * 64];    // W2 [k][col] (8 KB)
    int tid  = threadIdx.x;
    int base = blockIdx.x * 64;

    for (int i = tid; i < 32 * 64; i += 128) ws[i] = W2[i];
    for (int i = tid; i < 64 * 32; i += 128) {
        int node = i >> 5, k = i & 31;
        as_[k * 68 + node] =
            (base + node < n) ? g_a2[(base + node) * FMID + k] : 0.0f;
    }
    __syncthreads();

    int warp = tid >> 5, lane = tid & 31;
    int n0 = warp * 16 + (lane >> 3) * 4;   // node offset in block tile
    int c0 = (lane & 7) * 8;                // col offset

    float acc[4][8];
#pragma unroll
    for (int i = 0; i < 4; i++)
#pragma unroll
        for (int j = 0; j < 8; j++) acc[i][j] = 0.0f;

#pragma unroll 8
    for (int k = 0; k < 32; k++) {
        float4 xv = *reinterpret_cast<const float4*>(&as_[k * 68 + n0]);
        float4 wa = *reinterpret_cast<const float4*>(&ws[k * 64 + c0]);
        float4 wb = *reinterpret_cast<const float4*>(&ws[k * 64 + c0 + 4]);
        float xr[4] = {xv.x, xv.y, xv.z, xv.w};
        float wr[8] = {wa.x, wa.y, wa.z, wa.w, wb.x, wb.y, wb.z, wb.w};
#pragma unroll
        for (int i = 0; i < 4; i++)
#pragma unroll
            for (int j = 0; j < 8; j++) acc[i][j] += xr[i] * wr[j];
    }

    float4 ba  = *reinterpret_cast<const float4*>(&b2[c0]);
    float4 bbv = *reinterpret_cast<const float4*>(&b2[c0 + 4]);
#pragma unroll
    for (int i = 0; i < 4; i++) {
        int node = base + n0 + i;
        if (node >= n) break;
        *reinterpret_cast<float4*>(&out[node * FIN + c0]) =
            make_float4(acc[i][0] + ba.x, acc[i][1] + ba.y,
                        acc[i][2] + ba.z, acc[i][3] + ba.w);
        *reinterpret_cast<float4*>(&out[node * FIN + c0 + 4]) =
            make_float4(acc[i][4] + bbv.x, acc[i][5] + bbv.y,
                        acc[i][6] + bbv.z, acc[i][7] + bbv.w);
    }
}

// ---------------------------------------------------------------------------
extern "C" void kernel_launch(void* const* d_in, const int* in_sizes, int n_in,
                              void* d_out, int out_size) {
    const float* x  = (const float*)d_in[0];
    const void*  ei = d_in[1];                 // edge_index [2,E], int32
    const float* W1 = (const float*)d_in[2];
    const float* b1 = (const float*)d_in[3];
    const float* W2 = (const float*)d_in[4];
    const float* b2 = (const float*)d_in[5];
    float*       out = (float*)d_out;

    const int N = in_sizes[0] / FIN;   // 100000
    const int E = in_sizes[1] / 2;     // 1200000

    const int T = 256;
    k_init     <<<(N + T - 1) / T, T>>>((const int*)ei, N);
    k_deg_count<<<(E + T - 1) / T, T>>>(ei, E);
    k_edge_fin <<<(E + T - 1) / T, T>>>(ei, E);

    k_gemm1    <<<(N + 127) / 128, 256>>>(x, W1, N);
    k_scatter32<<<(E * 8 + T - 1) / T, T>>>(0, E);

    k_relu     <<<(N * (FMID / 4) + T - 1) / T, T>>>(b1, N);
    k_scatter32<<<(E * 8 + T - 1) / T, T>>>(1, E);

    k_gemm2    <<<(N + 63) / 64, 128>>>(W2, b2, out, N);
}